// round 5
// baseline (speedup 1.0000x reference)
#include <cuda_runtime.h>
#include <math.h>
#include <stdint.h>

#define T     128
#define H     1024
#define INTER 4096
#define NE    8
#define NKCH  32          // 32 K-chunks of 32 floats = K slice of 1024 in both GEMMs

// ---------------- device-global scratch ----------------
__device__ int   g_cnt[NE];
__device__ int   g_tok[NE][T];
__device__ float g_coef[NE][T];
__device__ float g_act[NE][T][INTER];   // zero-init; pad rows never written => stay 0

// ---------------- smem layout (dynamic) ----------------
// [0,512)      toks (128 int)
// [512,1024)   coefs (128 float)
// [1024, +2*18432)   A stages: [2][128][36] floats
// [...,  +2*18432)   B stages: [2][128][36] floats
#define A_OFF   1024
#define B_OFF   (1024 + 2 * 18432)
#define SMEM_BYTES (1024 + 4 * 18432)   // 74752
#define ROWF 36                          // floats per padded row (32 data + 4 pad)
#define ROWB 144                         // bytes per padded row
#define STAGEB 18432                     // bytes per tile stage

// ---------------- PTX helpers ----------------
static __device__ __forceinline__ uint32_t smem_u32(const void* p){
    uint32_t a;
    asm("{ .reg .u64 t; cvta.to.shared.u64 t, %1; cvt.u32.u64 %0, t; }" : "=r"(a) : "l"(p));
    return a;
}
#define CP16(d, s)  asm volatile("cp.async.cg.shared.global [%0], [%1], 16;" :: "r"(d), "l"(s) : "memory")
#define CP_COMMIT() asm volatile("cp.async.commit_group;" ::: "memory")
#define CP_WAIT1()  asm volatile("cp.async.wait_group 1;" ::: "memory")
#define CP_WAIT0()  asm volatile("cp.async.wait_group 0;" ::: "memory")

static __device__ __forceinline__ uint32_t f2tf(float x){
    uint32_t r; asm("cvt.rna.tf32.f32 %0, %1;" : "=r"(r) : "f"(x)); return r;
}
static __device__ __forceinline__ void mma8(float* d, const uint32_t* a, const uint32_t* b){
    asm volatile("mma.sync.aligned.m16n8k8.row.col.f32.tf32.tf32.f32 "
        "{%0,%1,%2,%3}, {%4,%5,%6,%7}, {%8,%9}, {%0,%1,%2,%3};"
        : "+f"(d[0]), "+f"(d[1]), "+f"(d[2]), "+f"(d[3])
        : "r"(a[0]), "r"(a[1]), "r"(a[2]), "r"(a[3]), "r"(b[0]), "r"(b[1]));
}

// ---------------- kernel 0: zero output ----------------
__global__ void zero_out_kernel(float* __restrict__ out) {
    int i = blockIdx.x * blockDim.x + threadIdx.x;
    if (i < T * H) out[i] = 0.0f;
}

// ---------------- kernel 1: routing ----------------
__global__ void route_kernel(const float* __restrict__ routing) {
    __shared__ int s_cnt[NE];
    int t = threadIdx.x;
    if (t < NE) s_cnt[t] = 0;
    __syncthreads();
    float r[NE];
#pragma unroll
    for (int e = 0; e < NE; e++) r[e] = routing[t * NE + e];
    int i0 = 0;
#pragma unroll
    for (int e = 1; e < NE; e++) if (r[e] > r[i0]) i0 = e;
    int i1 = (i0 == 0) ? 1 : 0;
#pragma unroll
    for (int e = 0; e < NE; e++) if (e != i0 && r[e] > r[i1]) i1 = e;
    float d  = expf(r[i1] - r[i0]);
    float s0 = 1.0f / (1.0f + d);
    float s1 = d / (1.0f + d);
    int p0 = atomicAdd(&s_cnt[i0], 1);
    int p1 = atomicAdd(&s_cnt[i1], 1);
    g_tok[i0][p0] = t;  g_coef[i0][p0] = s0;
    g_tok[i1][p1] = t;  g_coef[i1][p1] = s1;
    __syncthreads();
    if (t < NE) g_cnt[t] = s_cnt[t];
}

// ================= shared GEMM machinery =================
// CTA tile: M=128 (tokens), N=128 (weight rows), K-chunk=32. 8 warps as 2(M)x4(N),
// warp tile 64x32, mma m16n8k8 tf32, fragments rounded via cvt.rna.

struct Frags {
    float acc[4][4][4];
};

static __device__ __forceinline__ void compute_chunk(const float* __restrict__ As,
                                                     const float* __restrict__ Bs,
                                                     int wm, int wn, int lane,
                                                     float (&acc)[4][4][4]) {
    int g0 = lane >> 2, t4 = lane & 3;
#pragma unroll
    for (int ks = 0; ks < 4; ks++) {
        int k0 = ks * 8 + t4;
        uint32_t a[4][4];
#pragma unroll
        for (int mf = 0; mf < 4; mf++) {
            int r0 = wm * 64 + mf * 16 + g0;
            a[mf][0] = f2tf(As[r0 * ROWF + k0]);
            a[mf][1] = f2tf(As[(r0 + 8) * ROWF + k0]);
            a[mf][2] = f2tf(As[r0 * ROWF + k0 + 4]);
            a[mf][3] = f2tf(As[(r0 + 8) * ROWF + k0 + 4]);
        }
        uint32_t b[4][2];
#pragma unroll
        for (int nf = 0; nf < 4; nf++) {
            int n = wn * 32 + nf * 8 + g0;
            b[nf][0] = f2tf(Bs[n * ROWF + k0]);
            b[nf][1] = f2tf(Bs[n * ROWF + k0 + 4]);
        }
#pragma unroll
        for (int mf = 0; mf < 4; mf++)
#pragma unroll
            for (int nf = 0; nf < 4; nf++)
                mma8(acc[mf][nf], a[mf], b[nf]);
    }
}

// ---------------- kernel 2: fc1 (mma tf32) + swiglu + coef fold ----------------
// grid (64, NE): 64 channel-tiles of 64 inter channels. B rows interleaved up/gate.
__global__ void __launch_bounds__(256, 2) fc1_mma(const float* __restrict__ x,
                                                  const float* __restrict__ w1) {
    extern __shared__ __align__(1024) char smem[];
    int*   toks  = (int*)smem;
    float* coefs = (float*)(smem + 512);
    float* Asm   = (float*)(smem + A_OFF);
    float* Bsm   = (float*)(smem + B_OFF);

    int tid = threadIdx.x, wid = tid >> 5, lane = tid & 31;
    int wm = wid >> 2, wn = wid & 3;
    int e   = blockIdx.y;
    int cnt = g_cnt[e];
    int ch0 = blockIdx.x * 64;     // first inter channel of this CTA

    if (tid < T) {
        toks[tid]  = (tid < cnt) ? g_tok[e][tid]  : 0;
        coefs[tid] = (tid < cnt) ? g_coef[e][tid] : 0.0f;
    }
    __syncthreads();

    // loader roles: 2 threads per row, 4x16B each
    int arow = tid >> 1, ab = (tid & 1) * 4;
    const float* aglob = x + (size_t)toks[arow] * H + ab * 4;
    int chan = arow >> 1;
    int wrow = (arow & 1) ? (INTER + ch0 + chan) : (ch0 + chan);   // odd rows = gate
    const float* bglob = w1 + (size_t)e * (2 * INTER) * H + (size_t)wrow * H + ab * 4;

    uint32_t aA = smem_u32(Asm) + arow * ROWB + ab * 16;
    uint32_t aB = smem_u32(Bsm) + arow * ROWB + ab * 16;

    float acc[4][4][4];
#pragma unroll
    for (int i = 0; i < 4; i++)
#pragma unroll
        for (int j = 0; j < 4; j++)
#pragma unroll
            for (int q = 0; q < 4; q++) acc[i][j][q] = 0.0f;

#define LOADC(i, st) do { \
        const float* _as = aglob + (i) * 32; \
        const float* _bs = bglob + (i) * 32; \
        uint32_t _ad = aA + (st) * STAGEB; \
        uint32_t _bd = aB + (st) * STAGEB; \
        CP16(_ad,      _as);      CP16(_ad + 16, _as + 4); \
        CP16(_ad + 32, _as + 8);  CP16(_ad + 48, _as + 12); \
        CP16(_bd,      _bs);      CP16(_bd + 16, _bs + 4); \
        CP16(_bd + 32, _bs + 8);  CP16(_bd + 48, _bs + 12); \
    } while (0)

    LOADC(0, 0); CP_COMMIT();
    LOADC(1, 1); CP_COMMIT();

    for (int i = 0; i < NKCH; i++) {
        int st = i & 1;
        if (i + 1 < NKCH) { CP_WAIT1(); } else { CP_WAIT0(); }
        __syncthreads();
        compute_chunk(Asm + st * (STAGEB / 4), Bsm + st * (STAGEB / 4), wm, wn, lane, acc);
        __syncthreads();
        if (i + 2 < NKCH) { LOADC(i + 2, st); CP_COMMIT(); }
    }

    // epilogue: (c0,c1)=(up,gate) for one channel; swiglu, fold coef, store to g_act
    int g0 = lane >> 2, t4 = lane & 3;
#pragma unroll
    for (int mf = 0; mf < 4; mf++) {
        int m0 = wm * 64 + mf * 16 + g0;
#pragma unroll
        for (int nf = 0; nf < 4; nf++) {
            int ch = ch0 + wn * 16 + nf * 4 + t4;
            float u0 = acc[mf][nf][0], gg0 = acc[mf][nf][1];
            float u1 = acc[mf][nf][2], gg1 = acc[mf][nf][3];
            if (m0 < cnt)
                g_act[e][m0][ch]     = coefs[m0]     * (u0 / (1.0f + __expf(-u0))) * gg0;
            if (m0 + 8 < cnt)
                g_act[e][m0 + 8][ch] = coefs[m0 + 8] * (u1 / (1.0f + __expf(-u1))) * gg1;
        }
    }
#undef LOADC
}

// ---------------- kernel 3: fc2 (mma tf32, 4-way K-split) + scatter-add ----------
// grid (8, 4, NE): 8 hidden-tiles of 128, 4 K-slices of 1024.
__global__ void __launch_bounds__(256, 2) fc2_mma(const float* __restrict__ w2,
                                                  float* __restrict__ out) {
    extern __shared__ __align__(1024) char smem[];
    int*   toks = (int*)smem;
    float* Asm  = (float*)(smem + A_OFF);
    float* Bsm  = (float*)(smem + B_OFF);

    int tid = threadIdx.x, wid = tid >> 5, lane = tid & 31;
    int wm = wid >> 2, wn = wid & 3;
    int e     = blockIdx.z;
    int cnt   = g_cnt[e];
    int n0    = blockIdx.x * 128;
    int kbase = blockIdx.y * 1024;

    if (tid < T) toks[tid] = (tid < cnt) ? g_tok[e][tid] : 0;
    __syncthreads();

    int arow = tid >> 1, ab = (tid & 1) * 4;
    const float* aglob = &g_act[e][arow][kbase] + ab * 4;
    const float* bglob = w2 + (size_t)e * H * INTER + (size_t)(n0 + arow) * INTER + kbase + ab * 4;

    uint32_t aA = smem_u32(Asm) + arow * ROWB + ab * 16;
    uint32_t aB = smem_u32(Bsm) + arow * ROWB + ab * 16;

    float acc[4][4][4];
#pragma unroll
    for (int i = 0; i < 4; i++)
#pragma unroll
        for (int j = 0; j < 4; j++)
#pragma unroll
            for (int q = 0; q < 4; q++) acc[i][j][q] = 0.0f;

#define LOADC(i, st) do { \
        const float* _as = aglob + (i) * 32; \
        const float* _bs = bglob + (i) * 32; \
        uint32_t _ad = aA + (st) * STAGEB; \
        uint32_t _bd = aB + (st) * STAGEB; \
        CP16(_ad,      _as);      CP16(_ad + 16, _as + 4); \
        CP16(_ad + 32, _as + 8);  CP16(_ad + 48, _as + 12); \
        CP16(_bd,      _bs);      CP16(_bd + 16, _bs + 4); \
        CP16(_bd + 32, _bs + 8);  CP16(_bd + 48, _bs + 12); \
    } while (0)

    LOADC(0, 0); CP_COMMIT();
    LOADC(1, 1); CP_COMMIT();

    for (int i = 0; i < NKCH; i++) {
        int st = i & 1;
        if (i + 1 < NKCH) { CP_WAIT1(); } else { CP_WAIT0(); }
        __syncthreads();
        compute_chunk(Asm + st * (STAGEB / 4), Bsm + st * (STAGEB / 4), wm, wn, lane, acc);
        __syncthreads();
        if (i + 2 < NKCH) { LOADC(i + 2, st); CP_COMMIT(); }
    }

    // epilogue: coef already folded into activations; scatter-add partial sums
    int g0 = lane >> 2, t4 = lane & 3;
#pragma unroll
    for (int mf = 0; mf < 4; mf++) {
        int m0 = wm * 64 + mf * 16 + g0;
#pragma unroll
        for (int nf = 0; nf < 4; nf++) {
            int n = n0 + wn * 32 + nf * 8 + 2 * t4;
            if (m0 < cnt) {
                float* o = out + (size_t)toks[m0] * H + n;
                atomicAdd(o,     acc[mf][nf][0]);
                atomicAdd(o + 1, acc[mf][nf][1]);
            }
            if (m0 + 8 < cnt) {
                float* o = out + (size_t)toks[m0 + 8] * H + n;
                atomicAdd(o,     acc[mf][nf][2]);
                atomicAdd(o + 1, acc[mf][nf][3]);
            }
        }
    }
#undef LOADC
}

// ---------------- launch ----------------
extern "C" void kernel_launch(void* const* d_in, const int* in_sizes, int n_in,
                              void* d_out, int out_size) {
    const float* x       = (const float*)d_in[0];   // [128, 1024]
    const float* routing = (const float*)d_in[1];   // [128, 8]
    const float* w1      = (const float*)d_in[2];   // [8, 8192, 1024]
    const float* w2      = (const float*)d_in[3];   // [8, 1024, 4096]
    float* out = (float*)d_out;                     // [128, 1024]

    cudaFuncSetAttribute(fc1_mma, cudaFuncAttributeMaxDynamicSharedMemorySize, SMEM_BYTES);
    cudaFuncSetAttribute(fc2_mma, cudaFuncAttributeMaxDynamicSharedMemorySize, SMEM_BYTES);

    zero_out_kernel<<<(T * H + 255) / 256, 256>>>(out);
    route_kernel<<<1, T>>>(routing);
    fc1_mma<<<dim3(64, NE), 256, SMEM_BYTES>>>(x, w1);
    fc2_mma<<<dim3(8, 4, NE), 256, SMEM_BYTES>>>(w2, out);
}

// round 6
// speedup vs baseline: 2.8073x; 2.8073x over previous
#include <cuda_runtime.h>
#include <math.h>
#include <stdint.h>

#define T     128
#define H     1024
#define INTER 4096
#define NE    8
#define NKCH  32          // 32 K-chunks of 32 floats = K depth of 1024 per CTA

// ---------------- device-global scratch ----------------
__device__ int   g_cnt[NE];
__device__ int   g_tok[NE][T];
__device__ float g_coef[NE][T];          // pad slots never written -> stay 0
__device__ float g_xg[NE][T][H];         // gathered token rows (4 MB)
__device__ float g_h[NE][T][2 * INTER];  // raw fc1 output (33.5 MB)
__device__ float g_act[NE][T][INTER];    // coef-scaled swiglu output (16.8 MB)

// ---------------- smem layout (dynamic) ----------------
#define A_OFF   1024
#define B_OFF   (1024 + 2 * 18432)
#define SMEM_BYTES (1024 + 4 * 18432)   // 74752
#define ROWF 36                          // floats per padded row (32 data + 4 pad)
#define ROWB 144
#define STAGEB 18432

// ---------------- PTX helpers ----------------
static __device__ __forceinline__ uint32_t smem_u32(const void* p){
    uint32_t a;
    asm("{ .reg .u64 t; cvta.to.shared.u64 t, %1; cvt.u32.u64 %0, t; }" : "=r"(a) : "l"(p));
    return a;
}
#define CP16(d, s)  asm volatile("cp.async.cg.shared.global [%0], [%1], 16;" :: "r"(d), "l"(s) : "memory")
#define CP_COMMIT() asm volatile("cp.async.commit_group;" ::: "memory")
#define CP_WAIT1()  asm volatile("cp.async.wait_group 1;" ::: "memory")
#define CP_WAIT0()  asm volatile("cp.async.wait_group 0;" ::: "memory")

static __device__ __forceinline__ uint32_t f2tf(float x){
    uint32_t r; asm("cvt.rna.tf32.f32 %0, %1;" : "=r"(r) : "f"(x)); return r;
}
static __device__ __forceinline__ void mma8(float* d, const uint32_t* a, const uint32_t* b){
    asm volatile("mma.sync.aligned.m16n8k8.row.col.f32.tf32.tf32.f32 "
        "{%0,%1,%2,%3}, {%4,%5,%6,%7}, {%8,%9}, {%0,%1,%2,%3};"
        : "+f"(d[0]), "+f"(d[1]), "+f"(d[2]), "+f"(d[3])
        : "r"(a[0]), "r"(a[1]), "r"(a[2]), "r"(a[3]), "r"(b[0]), "r"(b[1]));
}

// ---------------- kernel 0: zero output ----------------
__global__ void zero_out_kernel(float* __restrict__ out) {
    int i = blockIdx.x * blockDim.x + threadIdx.x;
    if (i < T * H) out[i] = 0.0f;
}

// ---------------- kernel 1: routing ----------------
__global__ void route_kernel(const float* __restrict__ routing) {
    __shared__ int s_cnt[NE];
    int t = threadIdx.x;
    if (t < NE) s_cnt[t] = 0;
    __syncthreads();
    float r[NE];
#pragma unroll
    for (int e = 0; e < NE; e++) r[e] = routing[t * NE + e];
    int i0 = 0;
#pragma unroll
    for (int e = 1; e < NE; e++) if (r[e] > r[i0]) i0 = e;
    int i1 = (i0 == 0) ? 1 : 0;
#pragma unroll
    for (int e = 0; e < NE; e++) if (e != i0 && r[e] > r[i1]) i1 = e;
    float d  = expf(r[i1] - r[i0]);
    float s0 = 1.0f / (1.0f + d);
    float s1 = d / (1.0f + d);
    int p0 = atomicAdd(&s_cnt[i0], 1);
    int p1 = atomicAdd(&s_cnt[i1], 1);
    g_tok[i0][p0] = t;  g_coef[i0][p0] = s0;
    g_tok[i1][p1] = t;  g_coef[i1][p1] = s1;
    __syncthreads();
    if (t < NE) g_cnt[t] = s_cnt[t];
}

// ---------------- kernel 2: gather token rows -> g_xg ----------------
// grid NE*T blocks of 256; block = one (e, m) row; float4 copies.
__global__ void gather_x_kernel(const float* __restrict__ x) {
    int bid = blockIdx.x;
    int e = bid >> 7, m = bid & 127;
    int tok = (m < g_cnt[e]) ? g_tok[e][m] : 0;
    const float4* src = (const float4*)(x + (size_t)tok * H);
    float4* dst = (float4*)&g_xg[e][m][0];
    dst[threadIdx.x] = src[threadIdx.x];
}

// ================= shared GEMM tile machinery =================
// CTA tile M=128 x N=128 x Kchunk=32, 8 warps as 2(M) x 4(N), warp tile 64x32.
static __device__ __forceinline__ void compute_chunk(const float* __restrict__ As,
                                                     const float* __restrict__ Bs,
                                                     int wm, int wn, int lane,
                                                     float (&acc)[4][4][4]) {
    int g0 = lane >> 2, t4 = lane & 3;
#pragma unroll
    for (int ks = 0; ks < 4; ks++) {
        int k0 = ks * 8 + t4;
        uint32_t a[4][4];
#pragma unroll
        for (int mf = 0; mf < 4; mf++) {
            int r0 = wm * 64 + mf * 16 + g0;
            a[mf][0] = f2tf(As[r0 * ROWF + k0]);
            a[mf][1] = f2tf(As[(r0 + 8) * ROWF + k0]);
            a[mf][2] = f2tf(As[r0 * ROWF + k0 + 4]);
            a[mf][3] = f2tf(As[(r0 + 8) * ROWF + k0 + 4]);
        }
        uint32_t b[4][2];
#pragma unroll
        for (int nf = 0; nf < 4; nf++) {
            int n = wn * 32 + nf * 8 + g0;
            b[nf][0] = f2tf(Bs[n * ROWF + k0]);
            b[nf][1] = f2tf(Bs[n * ROWF + k0 + 4]);
        }
#pragma unroll
        for (int mf = 0; mf < 4; mf++)
#pragma unroll
            for (int nf = 0; nf < 4; nf++)
                mma8(acc[mf][nf], a[mf], b[nf]);
    }
}

#define GEMM_PROLOG() \
    float acc[4][4][4]; \
    _Pragma("unroll") for (int _i = 0; _i < 4; _i++) \
    _Pragma("unroll") for (int _j = 0; _j < 4; _j++) \
    _Pragma("unroll") for (int _q = 0; _q < 4; _q++) acc[_i][_j][_q] = 0.0f;

#define LOADC(i, st) do { \
        const float* _as = aglob + (i) * 32; \
        const float* _bs = bglob + (i) * 32; \
        uint32_t _ad = aA + (st) * STAGEB; \
        uint32_t _bd = aB + (st) * STAGEB; \
        CP16(_ad,      _as);      CP16(_ad + 16, _as + 4); \
        CP16(_ad + 32, _as + 8);  CP16(_ad + 48, _as + 12); \
        CP16(_bd,      _bs);      CP16(_bd + 16, _bs + 4); \
        CP16(_bd + 32, _bs + 8);  CP16(_bd + 48, _bs + 12); \
    } while (0)

#define GEMM_MAINLOOP() \
    LOADC(0, 0); CP_COMMIT(); \
    LOADC(1, 1); CP_COMMIT(); \
    for (int i = 0; i < NKCH; i++) { \
        int st = i & 1; \
        if (i + 1 < NKCH) { CP_WAIT1(); } else { CP_WAIT0(); } \
        __syncthreads(); \
        compute_chunk(Asm + st * (STAGEB / 4), Bsm + st * (STAGEB / 4), wm, wn, lane, acc); \
        __syncthreads(); \
        if (i + 2 < NKCH) { LOADC(i + 2, st); CP_COMMIT(); } \
    }

// ---------------- kernel 3: fc1 GEMM (raw h, no epilogue math) ----------------
// grid (64, NE): n-tile = 128 contiguous rows of w1[e] (8192 rows total).
__global__ void __launch_bounds__(256, 2) fc1_mma(const float* __restrict__ w1) {
    extern __shared__ __align__(1024) char smem[];
    float* Asm = (float*)(smem + A_OFF);
    float* Bsm = (float*)(smem + B_OFF);

    int tid = threadIdx.x, wid = tid >> 5, lane = tid & 31;
    int wm = wid >> 2, wn = wid & 3;
    int e  = blockIdx.y;
    int n0 = blockIdx.x * 128;

    int arow = tid >> 1, ab = (tid & 1) * 4;
    const float* aglob = &g_xg[e][arow][0] + ab * 4;
    const float* bglob = w1 + (size_t)e * (2 * INTER) * H + (size_t)(n0 + arow) * H + ab * 4;

    uint32_t aA = smem_u32(Asm) + arow * ROWB + ab * 16;
    uint32_t aB = smem_u32(Bsm) + arow * ROWB + ab * 16;

    GEMM_PROLOG();
    GEMM_MAINLOOP();

    // plain store of raw GEMM result (pads included; zeroed later by coef=0)
    int g0 = lane >> 2, t4 = lane & 3;
#pragma unroll
    for (int mf = 0; mf < 4; mf++) {
        int m0 = wm * 64 + mf * 16 + g0;
#pragma unroll
        for (int nf = 0; nf < 4; nf++) {
            int n = n0 + wn * 32 + nf * 8 + 2 * t4;
            float* h0 = &g_h[e][m0][n];
            h0[0] = acc[mf][nf][0];
            h0[1] = acc[mf][nf][1];
            float* h1 = &g_h[e][m0 + 8][n];
            h1[0] = acc[mf][nf][2];
            h1[1] = acc[mf][nf][3];
        }
    }
}

// ---------------- kernel 4: swiglu + coef fold (elementwise) ----------------
// act[e][m][ch] = coef[e][m] * silu(h[e][m][ch]) * h[e][m][INTER+ch]
__global__ void swiglu_kernel() {
    int i4 = blockIdx.x * blockDim.x + threadIdx.x;   // float4 index
    int ch4 = i4 & (INTER / 4 - 1);
    int m   = (i4 >> 10) & (T - 1);
    int e   = i4 >> 17;
    float c = g_coef[e][m];
    float4 u = *(const float4*)&g_h[e][m][ch4 * 4];
    float4 g = *(const float4*)&g_h[e][m][INTER + ch4 * 4];
    float4 o;
    o.x = c * (u.x / (1.0f + __expf(-u.x))) * g.x;
    o.y = c * (u.y / (1.0f + __expf(-u.y))) * g.y;
    o.z = c * (u.z / (1.0f + __expf(-u.z))) * g.z;
    o.w = c * (u.w / (1.0f + __expf(-u.w))) * g.w;
    *(float4*)&g_act[e][m][ch4 * 4] = o;
}

// ---------------- kernel 5: fc2 GEMM (4-way K-split) + scatter-add ----------------
// grid (8, 4, NE): 8 hidden-tiles of 128, 4 K-slices of 1024.
__global__ void __launch_bounds__(256, 2) fc2_mma(const float* __restrict__ w2,
                                                  float* __restrict__ out) {
    extern __shared__ __align__(1024) char smem[];
    int*   toks = (int*)smem;
    float* Asm  = (float*)(smem + A_OFF);
    float* Bsm  = (float*)(smem + B_OFF);

    int tid = threadIdx.x, wid = tid >> 5, lane = tid & 31;
    int wm = wid >> 2, wn = wid & 3;
    int e     = blockIdx.z;
    int cnt   = g_cnt[e];
    int n0    = blockIdx.x * 128;
    int kbase = blockIdx.y * 1024;

    if (tid < T) toks[tid] = (tid < cnt) ? g_tok[e][tid] : 0;
    __syncthreads();

    int arow = tid >> 1, ab = (tid & 1) * 4;
    const float* aglob = &g_act[e][arow][kbase] + ab * 4;
    const float* bglob = w2 + (size_t)e * H * INTER + (size_t)(n0 + arow) * INTER + kbase + ab * 4;

    uint32_t aA = smem_u32(Asm) + arow * ROWB + ab * 16;
    uint32_t aB = smem_u32(Bsm) + arow * ROWB + ab * 16;

    GEMM_PROLOG();
    GEMM_MAINLOOP();

    int g0 = lane >> 2, t4 = lane & 3;
#pragma unroll
    for (int mf = 0; mf < 4; mf++) {
        int m0 = wm * 64 + mf * 16 + g0;
#pragma unroll
        for (int nf = 0; nf < 4; nf++) {
            int n = n0 + wn * 32 + nf * 8 + 2 * t4;
            if (m0 < cnt) {
                float* o = out + (size_t)toks[m0] * H + n;
                atomicAdd(o,     acc[mf][nf][0]);
                atomicAdd(o + 1, acc[mf][nf][1]);
            }
            if (m0 + 8 < cnt) {
                float* o = out + (size_t)toks[m0 + 8] * H + n;
                atomicAdd(o,     acc[mf][nf][2]);
                atomicAdd(o + 1, acc[mf][nf][3]);
            }
        }
    }
}

// ---------------- launch ----------------
extern "C" void kernel_launch(void* const* d_in, const int* in_sizes, int n_in,
                              void* d_out, int out_size) {
    const float* x       = (const float*)d_in[0];   // [128, 1024]
    const float* routing = (const float*)d_in[1];   // [128, 8]
    const float* w1      = (const float*)d_in[2];   // [8, 8192, 1024]
    const float* w2      = (const float*)d_in[3];   // [8, 1024, 4096]
    float* out = (float*)d_out;                     // [128, 1024]

    cudaFuncSetAttribute(fc1_mma, cudaFuncAttributeMaxDynamicSharedMemorySize, SMEM_BYTES);
    cudaFuncSetAttribute(fc2_mma, cudaFuncAttributeMaxDynamicSharedMemorySize, SMEM_BYTES);

    zero_out_kernel<<<(T * H + 255) / 256, 256>>>(out);
    route_kernel<<<1, T>>>(routing);
    gather_x_kernel<<<NE * T, 256>>>(x);
    fc1_mma<<<dim3(64, NE), 256, SMEM_BYTES>>>(w1);
    swiglu_kernel<<<(NE * T * INTER / 4) / 256, 256>>>();
    fc2_mma<<<dim3(8, 4, NE), 256, SMEM_BYTES>>>(w2, out);
}

// round 7
// speedup vs baseline: 3.1970x; 1.1388x over previous
#include <cuda_runtime.h>
#include <math.h>
#include <stdint.h>

#define T     128
#define H     1024
#define INTER 4096
#define NE    8
#define NKCH  32          // 32 K-chunks of 32 floats = K depth 1024 per CTA

// ---------------- device-global scratch ----------------
__device__ int   g_cnt[NE];
__device__ int   g_tok[NE][T];
__device__ float g_coef[NE][T];          // pad slots never written -> stay 0
__device__ float g_xg[NE][T][H];         // gathered token rows (4 MB)
__device__ float g_act[NE][T][INTER];    // coef-scaled swiglu output (16.8 MB)

// ---------------- smem layout (dynamic) ----------------
// [0,512)    coefs (fc1) / toks (fc2)
// [1024, +3*16384)  A stages   [B_OFF, +3*16384) B stages
#define A_OFF   1024
#define B_OFF   (1024 + 3 * 16384)
#define SMEM_BYTES (1024 + 6 * 16384)   // 99328
#define STAGEB 16384                     // 128 rows x 128 B, XOR-swizzled

// ---------------- PTX helpers ----------------
static __device__ __forceinline__ uint32_t smem_u32(const void* p){
    uint32_t a;
    asm("{ .reg .u64 t; cvta.to.shared.u64 t, %1; cvt.u32.u64 %0, t; }" : "=r"(a) : "l"(p));
    return a;
}
#define CP16(d, s)  asm volatile("cp.async.cg.shared.global [%0], [%1], 16;" :: "r"(d), "l"(s) : "memory")
#define CP_COMMIT() asm volatile("cp.async.commit_group;" ::: "memory")
#define CP_WAIT1()  asm volatile("cp.async.wait_group 1;" ::: "memory")
#define CP_WAIT0()  asm volatile("cp.async.wait_group 0;" ::: "memory")

static __device__ __forceinline__ uint32_t f2tf(float x){
    uint32_t r; asm("cvt.rna.tf32.f32 %0, %1;" : "=r"(r) : "f"(x)); return r;
}
static __device__ __forceinline__ void mma8(float* d, const uint32_t* a, const uint32_t* b){
    asm volatile("mma.sync.aligned.m16n8k8.row.col.f32.tf32.tf32.f32 "
        "{%0,%1,%2,%3}, {%4,%5,%6,%7}, {%8,%9}, {%0,%1,%2,%3};"
        : "+f"(d[0]), "+f"(d[1]), "+f"(d[2]), "+f"(d[3])
        : "r"(a[0]), "r"(a[1]), "r"(a[2]), "r"(a[3]), "r"(b[0]), "r"(b[1]));
}

// ---------------- kernel 0: zero output ----------------
__global__ void zero_out_kernel(float* __restrict__ out) {
    int i = blockIdx.x * blockDim.x + threadIdx.x;
    if (i < T * H) out[i] = 0.0f;
}

// ---------------- kernel 1: routing ----------------
__global__ void route_kernel(const float* __restrict__ routing) {
    __shared__ int s_cnt[NE];
    int t = threadIdx.x;
    if (t < NE) s_cnt[t] = 0;
    __syncthreads();
    float r[NE];
#pragma unroll
    for (int e = 0; e < NE; e++) r[e] = routing[t * NE + e];
    int i0 = 0;
#pragma unroll
    for (int e = 1; e < NE; e++) if (r[e] > r[i0]) i0 = e;
    int i1 = (i0 == 0) ? 1 : 0;
#pragma unroll
    for (int e = 0; e < NE; e++) if (e != i0 && r[e] > r[i1]) i1 = e;
    float d  = expf(r[i1] - r[i0]);
    float s0 = 1.0f / (1.0f + d);
    float s1 = d / (1.0f + d);
    int p0 = atomicAdd(&s_cnt[i0], 1);
    int p1 = atomicAdd(&s_cnt[i1], 1);
    g_tok[i0][p0] = t;  g_coef[i0][p0] = s0;
    g_tok[i1][p1] = t;  g_coef[i1][p1] = s1;
    __syncthreads();
    if (t < NE) g_cnt[t] = s_cnt[t];
}

// ---------------- kernel 2: gather token rows -> g_xg ----------------
__global__ void gather_x_kernel(const float* __restrict__ x) {
    int bid = blockIdx.x;
    int e = bid >> 7, m = bid & 127;
    int tok = (m < g_cnt[e]) ? g_tok[e][m] : 0;
    const float4* src = (const float4*)(x + (size_t)tok * H);
    float4* dst = (float4*)&g_xg[e][m][0];
    dst[threadIdx.x] = src[threadIdx.x];
}

// ================= shared GEMM tile machinery =================
// CTA tile M=128 x N=128 x Kchunk=32, 8 warps as 2(M) x 4(N), warp tile 64x32.
// XOR swizzle: float (r, k) lives at r*32 + (((k>>2) ^ (r&7))<<2) + (k&3).
// All fragment rows have r&7 == g0, so the xor term collapses per (ks, g0).
static __device__ __forceinline__ void compute_chunk(const float* __restrict__ As,
                                                     const float* __restrict__ Bs,
                                                     int wm, int wn, int lane,
                                                     float (&acc)[4][4][4]) {
    int g0 = lane >> 2, t4 = lane & 3;
#pragma unroll
    for (int ks = 0; ks < 4; ks++) {
        int c0 = (((2 * ks)     ^ g0) << 2) + t4;
        int c1 = (((2 * ks + 1) ^ g0) << 2) + t4;
        uint32_t a[4][4];
#pragma unroll
        for (int mf = 0; mf < 4; mf++) {
            int r0 = (wm * 64 + mf * 16 + g0) * 32;
            a[mf][0] = f2tf(As[r0 + c0]);
            a[mf][1] = f2tf(As[r0 + 256 + c0]);   // +8 rows
            a[mf][2] = f2tf(As[r0 + c1]);
            a[mf][3] = f2tf(As[r0 + 256 + c1]);
        }
        uint32_t b[4][2];
#pragma unroll
        for (int nf = 0; nf < 4; nf++) {
            int n = (wn * 32 + nf * 8 + g0) * 32;
            b[nf][0] = f2tf(Bs[n + c0]);
            b[nf][1] = f2tf(Bs[n + c1]);
        }
#pragma unroll
        for (int mf = 0; mf < 4; mf++)
#pragma unroll
            for (int nf = 0; nf < 4; nf++)
                mma8(acc[mf][nf], a[mf], b[nf]);
    }
}

#define GEMM_PROLOG() \
    float acc[4][4][4]; \
    _Pragma("unroll") for (int _i = 0; _i < 4; _i++) \
    _Pragma("unroll") for (int _j = 0; _j < 4; _j++) \
    _Pragma("unroll") for (int _q = 0; _q < 4; _q++) acc[_i][_j][_q] = 0.0f;

// per-thread loader: 4x16B of A + 4x16B of B per chunk, swizzled dst
#define LOADC(i, st) do { \
        const float* _as = aglob + (i) * 32; \
        const float* _bs = bglob + (i) * 32; \
        uint32_t _ad = aA + (st) * STAGEB; \
        uint32_t _bd = aB + (st) * STAGEB; \
        CP16(_ad + (((ab + 0) << 4) ^ sw), _as);      \
        CP16(_ad + (((ab + 1) << 4) ^ sw), _as + 4);  \
        CP16(_ad + (((ab + 2) << 4) ^ sw), _as + 8);  \
        CP16(_ad + (((ab + 3) << 4) ^ sw), _as + 12); \
        CP16(_bd + (((ab + 0) << 4) ^ sw), _bs);      \
        CP16(_bd + (((ab + 1) << 4) ^ sw), _bs + 4);  \
        CP16(_bd + (((ab + 2) << 4) ^ sw), _bs + 8);  \
        CP16(_bd + (((ab + 3) << 4) ^ sw), _bs + 12); \
    } while (0)

// 3-stage, load-before-compute, ONE barrier per chunk.
// Prologue fills stages 0,1. At iter i: chunk i ready (wait 1 outstanding),
// barrier (also proves compute i-1 done by all), issue load i+2 into the
// freed stage, then compute chunk i.
#define GEMM_MAINLOOP() \
    LOADC(0, 0); CP_COMMIT(); \
    LOADC(1, 1); CP_COMMIT(); \
    { \
        int st_c = 0, st_l = 2; \
        for (int i = 0; i < NKCH; i++) { \
            if (i < NKCH - 1) { CP_WAIT1(); } else { CP_WAIT0(); } \
            __syncthreads(); \
            if (i + 2 < NKCH) { LOADC(i + 2, st_l); CP_COMMIT(); if (++st_l == 3) st_l = 0; } \
            compute_chunk(Asm + st_c * (STAGEB / 4), Bsm + st_c * (STAGEB / 4), wm, wn, lane, acc); \
            if (++st_c == 3) st_c = 0; \
        } \
    }

// ---------------- kernel 3: fc1 GEMM + fused swiglu + coef fold ----------------
// grid (64, NE): n-tile = 64 channels; B rows = 64 up rows + 64 gate rows.
__global__ void __launch_bounds__(256, 2) fc1_mma(const float* __restrict__ w1) {
    extern __shared__ __align__(1024) char smem[];
    float* coefs = (float*)smem;
    float* Asm   = (float*)(smem + A_OFF);
    float* Bsm   = (float*)(smem + B_OFF);
    float* buf   = (float*)(smem + A_OFF);   // epilogue exchange, reuses stages

    int tid = threadIdx.x, wid = tid >> 5, lane = tid & 31;
    int wm = wid >> 2, wn = wid & 3;
    int e  = blockIdx.y;
    int n0 = blockIdx.x * 64;      // first inter channel of this CTA

    if (tid < T) coefs[tid] = g_coef[e][tid];   // pads = 0

    int arow = tid >> 1, ab = (tid & 1) * 4;
    uint32_t sw = (arow & 7) << 4;
    const float* aglob = &g_xg[e][arow][0] + ab * 4;
    int wrow = (arow < 64) ? (n0 + arow) : (INTER + n0 + (arow - 64));
    const float* bglob = w1 + (size_t)e * (2 * INTER) * H + (size_t)wrow * H + ab * 4;

    uint32_t aA = smem_u32(Asm) + arow * 128;
    uint32_t aB = smem_u32(Bsm) + arow * 128;

    GEMM_PROLOG();
    GEMM_MAINLOOP();

    // ---- epilogue: exchange through smem, swiglu + coef, store g_act ----
    __syncthreads();                      // all computes done before buf overwrite
    int g0 = lane >> 2, t4 = lane & 3;
#pragma unroll
    for (int mf = 0; mf < 4; mf++) {
        int m0 = wm * 64 + mf * 16 + g0;
#pragma unroll
        for (int nf = 0; nf < 4; nf++) {
            int j = wn * 32 + nf * 8 + 2 * t4;
            buf[m0 * 132 + j]           = acc[mf][nf][0];
            buf[m0 * 132 + j + 1]       = acc[mf][nf][1];
            buf[(m0 + 8) * 132 + j]     = acc[mf][nf][2];
            buf[(m0 + 8) * 132 + j + 1] = acc[mf][nf][3];
        }
    }
    __syncthreads();
    {
        int m  = tid >> 1;
        int jh = (tid & 1) << 5;          // 0 or 32
        float c = coefs[m];
        const float* row = &buf[m * 132];
#pragma unroll
        for (int q = 0; q < 8; q++) {
            float4 u = *(const float4*)&row[jh + q * 4];        // up   (cols 0..63)
            float4 g = *(const float4*)&row[64 + jh + q * 4];   // gate (cols 64..127)
            float4 o;
            o.x = c * (u.x / (1.0f + __expf(-u.x))) * g.x;
            o.y = c * (u.y / (1.0f + __expf(-u.y))) * g.y;
            o.z = c * (u.z / (1.0f + __expf(-u.z))) * g.z;
            o.w = c * (u.w / (1.0f + __expf(-u.w))) * g.w;
            *(float4*)&g_act[e][m][n0 + jh + q * 4] = o;
        }
    }
}

// ---------------- kernel 4: fc2 GEMM (4-way K-split) + scatter-add ----------------
// grid (8, 4, NE): 8 hidden-tiles of 128, 4 K-slices of 1024.
__global__ void __launch_bounds__(256, 2) fc2_mma(const float* __restrict__ w2,
                                                  float* __restrict__ out) {
    extern __shared__ __align__(1024) char smem[];
    int*   toks = (int*)smem;
    float* Asm  = (float*)(smem + A_OFF);
    float* Bsm  = (float*)(smem + B_OFF);

    int tid = threadIdx.x, wid = tid >> 5, lane = tid & 31;
    int wm = wid >> 2, wn = wid & 3;
    int e     = blockIdx.z;
    int cnt   = g_cnt[e];
    int n0    = blockIdx.x * 128;
    int kbase = blockIdx.y * 1024;

    if (tid < T) toks[tid] = (tid < cnt) ? g_tok[e][tid] : 0;

    int arow = tid >> 1, ab = (tid & 1) * 4;
    uint32_t sw = (arow & 7) << 4;
    const float* aglob = &g_act[e][arow][kbase] + ab * 4;
    const float* bglob = w2 + (size_t)e * H * INTER + (size_t)(n0 + arow) * INTER + kbase + ab * 4;

    uint32_t aA = smem_u32(Asm) + arow * 128;
    uint32_t aB = smem_u32(Bsm) + arow * 128;

    GEMM_PROLOG();
    GEMM_MAINLOOP();

    int g0 = lane >> 2, t4 = lane & 3;
#pragma unroll
    for (int mf = 0; mf < 4; mf++) {
        int m0 = wm * 64 + mf * 16 + g0;
#pragma unroll
        for (int nf = 0; nf < 4; nf++) {
            int n = n0 + wn * 32 + nf * 8 + 2 * t4;
            if (m0 < cnt) {
                float* o = out + (size_t)toks[m0] * H + n;
                atomicAdd(o,     acc[mf][nf][0]);
                atomicAdd(o + 1, acc[mf][nf][1]);
            }
            if (m0 + 8 < cnt) {
                float* o = out + (size_t)toks[m0 + 8] * H + n;
                atomicAdd(o,     acc[mf][nf][2]);
                atomicAdd(o + 1, acc[mf][nf][3]);
            }
        }
    }
}

// ---------------- launch ----------------
extern "C" void kernel_launch(void* const* d_in, const int* in_sizes, int n_in,
                              void* d_out, int out_size) {
    const float* x       = (const float*)d_in[0];   // [128, 1024]
    const float* routing = (const float*)d_in[1];   // [128, 8]
    const float* w1      = (const float*)d_in[2];   // [8, 8192, 1024]
    const float* w2      = (const float*)d_in[3];   // [8, 1024, 4096]
    float* out = (float*)d_out;                     // [128, 1024]

    cudaFuncSetAttribute(fc1_mma, cudaFuncAttributeMaxDynamicSharedMemorySize, SMEM_BYTES);
    cudaFuncSetAttribute(fc2_mma, cudaFuncAttributeMaxDynamicSharedMemorySize, SMEM_BYTES);

    zero_out_kernel<<<(T * H + 255) / 256, 256>>>(out);
    route_kernel<<<1, T>>>(routing);
    gather_x_kernel<<<NE * T, 256>>>(x);
    fc1_mma<<<dim3(64, NE), 256, SMEM_BYTES>>>(w1);
    fc2_mma<<<dim3(8, 4, NE), 256, SMEM_BYTES>>>(w2, out);
}

// round 8
// speedup vs baseline: 3.7287x; 1.1663x over previous
#include <cuda_runtime.h>
#include <math.h>
#include <stdint.h>

#define T     128
#define H     1024
#define INTER 4096
#define NE    8
#define NKCH  32          // 32 K-chunks of 32 floats = K depth 1024 per CTA

// ---------------- device-global scratch ----------------
__device__ int   g_cnt[NE];
__device__ int   g_tok[NE][T];
__device__ float g_coef[NE][T];          // pad slots never written -> stay 0
__device__ float g_xg[NE][T][H];         // gathered token rows, tf32-rounded (4 MB)
__device__ float g_act[NE][T][INTER];    // coef-scaled swiglu output, tf32-rounded

// ---------------- smem layout (dynamic) ----------------
// [0,512)   coefs (fc1) / toks (fc2)
// stages: 3 x 32KB, each = [A 16KB][B 16KB], XOR-swizzled 128B rows
#define ST_OFF   1024
#define STAGEB   32768
#define SMEM_BYTES (1024 + 3 * STAGEB)   // 99328

// ---------------- PTX helpers ----------------
static __device__ __forceinline__ uint32_t smem_u32(const void* p){
    uint32_t a;
    asm("{ .reg .u64 t; cvta.to.shared.u64 t, %1; cvt.u32.u64 %0, t; }" : "=r"(a) : "l"(p));
    return a;
}
#define CP16(d, s)  asm volatile("cp.async.cg.shared.global [%0], [%1], 16;" :: "r"(d), "l"(s) : "memory")
#define CP_COMMIT() asm volatile("cp.async.commit_group;" ::: "memory")
#define CP_WAIT1()  asm volatile("cp.async.wait_group 1;" ::: "memory")
#define CP_WAIT0()  asm volatile("cp.async.wait_group 0;" ::: "memory")

static __device__ __forceinline__ uint32_t f2tf(float x){
    uint32_t r; asm("cvt.rna.tf32.f32 %0, %1;" : "=r"(r) : "f"(x)); return r;
}
static __device__ __forceinline__ void sts_cvt(uint32_t addr, float4 v){
    uint32_t x0 = f2tf(v.x), x1 = f2tf(v.y), x2 = f2tf(v.z), x3 = f2tf(v.w);
    asm volatile("st.shared.v4.b32 [%0], {%1,%2,%3,%4};"
                 :: "r"(addr), "r"(x0), "r"(x1), "r"(x2), "r"(x3) : "memory");
}
#define LDM4(r, addr) \
    asm volatile("ldmatrix.sync.aligned.m8n8.x4.shared.b16 {%0,%1,%2,%3}, [%4];" \
        : "=r"((r)[0]), "=r"((r)[1]), "=r"((r)[2]), "=r"((r)[3]) : "r"(addr))

static __device__ __forceinline__ void mma8(float* d, const uint32_t* a, uint32_t b0, uint32_t b1){
    asm volatile("mma.sync.aligned.m16n8k8.row.col.f32.tf32.tf32.f32 "
        "{%0,%1,%2,%3}, {%4,%5,%6,%7}, {%8,%9}, {%0,%1,%2,%3};"
        : "+f"(d[0]), "+f"(d[1]), "+f"(d[2]), "+f"(d[3])
        : "r"(a[0]), "r"(a[1]), "r"(a[2]), "r"(a[3]), "r"(b0), "r"(b1));
}

// ---------------- kernel 0: zero output ----------------
__global__ void zero_out_kernel(float* __restrict__ out) {
    int i = blockIdx.x * blockDim.x + threadIdx.x;
    if (i < T * H) out[i] = 0.0f;
}

// ---------------- kernel 1: routing ----------------
__global__ void route_kernel(const float* __restrict__ routing) {
    __shared__ int s_cnt[NE];
    int t = threadIdx.x;
    if (t < NE) s_cnt[t] = 0;
    __syncthreads();
    float r[NE];
#pragma unroll
    for (int e = 0; e < NE; e++) r[e] = routing[t * NE + e];
    int i0 = 0;
#pragma unroll
    for (int e = 1; e < NE; e++) if (r[e] > r[i0]) i0 = e;
    int i1 = (i0 == 0) ? 1 : 0;
#pragma unroll
    for (int e = 0; e < NE; e++) if (e != i0 && r[e] > r[i1]) i1 = e;
    float d  = expf(r[i1] - r[i0]);
    float s0 = 1.0f / (1.0f + d);
    float s1 = d / (1.0f + d);
    int p0 = atomicAdd(&s_cnt[i0], 1);
    int p1 = atomicAdd(&s_cnt[i1], 1);
    g_tok[i0][p0] = t;  g_coef[i0][p0] = s0;
    g_tok[i1][p1] = t;  g_coef[i1][p1] = s1;
    __syncthreads();
    if (t < NE) g_cnt[t] = s_cnt[t];
}

// ---------------- kernel 2: gather token rows (tf32-rounded) -> g_xg ----------------
__global__ void gather_x_kernel(const float* __restrict__ x) {
    int bid = blockIdx.x;
    int e = bid >> 7, m = bid & 127;
    int tok = (m < g_cnt[e]) ? g_tok[e][m] : 0;
    float4 v = ((const float4*)(x + (size_t)tok * H))[threadIdx.x];
    uint4 o;
    o.x = f2tf(v.x); o.y = f2tf(v.y); o.z = f2tf(v.z); o.w = f2tf(v.w);
    ((uint4*)&g_xg[e][m][0])[threadIdx.x] = o;
}

// ================= GEMM machinery =================
// CTA tile M=128 x N=128 x Kchunk=32, 8 warps as 2(M) x 4(N), warp tile 64x32.
// Data in smem is ALREADY tf32-rounded. Fragments via ldmatrix.b16 (fp32 = b16 pair).
// XOR swizzle: 16B unit u of row r stored at u ^ (r & 7); fragment address for
// k-step ks is base ^ (ks << 5).
static __device__ __forceinline__ void compute_chunk(
        uint32_t a0, uint32_t a1, uint32_t a2, uint32_t a3,
        uint32_t b0a, uint32_t b1a, float (&acc)[4][4][4]) {
#pragma unroll
    for (int ks = 0; ks < 4; ks++) {
        uint32_t x = ks << 5;
        uint32_t a[4][4], b[2][4];
        LDM4(a[0], a0 ^ x); LDM4(a[1], a1 ^ x);
        LDM4(a[2], a2 ^ x); LDM4(a[3], a3 ^ x);
        LDM4(b[0], b0a ^ x); LDM4(b[1], b1a ^ x);
#pragma unroll
        for (int mf = 0; mf < 4; mf++) {
#pragma unroll
            for (int p = 0; p < 2; p++) {
                mma8(acc[mf][2 * p],     a[mf], b[p][0], b[p][1]);
                mma8(acc[mf][2 * p + 1], a[mf], b[p][2], b[p][3]);
            }
        }
    }
}

#define GEMM_SETUP() \
    int tid = threadIdx.x, wid = tid >> 5, lane = tid & 31; \
    int wm = wid >> 2, wn = wid & 3; \
    int arow = tid >> 1, ab = (tid & 1) * 4; \
    uint32_t swu = arow & 7; \
    uint32_t smemA = smem_u32(smem) + ST_OFF; \
    uint32_t smemB = smemA + 16384; \
    int ls = lane & 7, h3 = (lane >> 3) & 1, h4 = (lane >> 4) & 1; \
    uint32_t aAf0 = smemA + (uint32_t)(wm * 64 + 0  + ls + 8 * h3) * 128 + ((uint32_t)(ls ^ h4) << 4); \
    uint32_t aAf1 = aAf0 + 16 * 128; \
    uint32_t aAf2 = aAf0 + 32 * 128; \
    uint32_t aAf3 = aAf0 + 48 * 128; \
    uint32_t aBf0 = smemB + (uint32_t)(wn * 32 + ls + 8 * h4) * 128 + ((uint32_t)(ls ^ h3) << 4); \
    uint32_t aBf1 = aBf0 + 16 * 128; \
    float4 rb0, rb1, rb2, rb3; \
    float acc[4][4][4]; \
    _Pragma("unroll") for (int _i = 0; _i < 4; _i++) \
    _Pragma("unroll") for (int _j = 0; _j < 4; _j++) \
    _Pragma("unroll") for (int _q = 0; _q < 4; _q++) acc[_i][_j][_q] = 0.0f;

#define CPA(i, st) do { \
        const float* _s = aglob + (i) * 32; \
        uint32_t _d = smemA + (st) * STAGEB + arow * 128; \
        CP16(_d + (((ab + 0) ^ swu) << 4), _s); \
        CP16(_d + (((ab + 1) ^ swu) << 4), _s + 4); \
        CP16(_d + (((ab + 2) ^ swu) << 4), _s + 8); \
        CP16(_d + (((ab + 3) ^ swu) << 4), _s + 12); \
    } while (0)

#define LDGB(i) do { \
        const float4* _p = (const float4*)(bglob + (i) * 32); \
        rb0 = _p[0]; rb1 = _p[1]; rb2 = _p[2]; rb3 = _p[3]; \
    } while (0)

#define STSB(st) do { \
        uint32_t _d = smemB + (st) * STAGEB + arow * 128; \
        sts_cvt(_d + (((ab + 0) ^ swu) << 4), rb0); \
        sts_cvt(_d + (((ab + 1) ^ swu) << 4), rb1); \
        sts_cvt(_d + (((ab + 2) ^ swu) << 4), rb2); \
        sts_cvt(_d + (((ab + 3) ^ swu) << 4), rb3); \
    } while (0)

// 3 stages, 1 barrier/chunk. A via cp.async (pre-rounded source), B via
// LDG -> cvt.rna -> STS riding registers one iteration.
#define GEMM_MAINLOOP() \
    LDGB(0); CPA(0, 0); CP_COMMIT(); \
    STSB(0); \
    LDGB(1); CPA(1, 1); CP_COMMIT(); \
    { \
        int stc = 0; \
        for (int i = 0; i < NKCH; i++) { \
            if (i < NKCH - 1) { CP_WAIT1(); } else { CP_WAIT0(); } \
            __syncthreads(); \
            int st1 = stc + 1; if (st1 == 3) st1 = 0; \
            int st2 = st1 + 1; if (st2 == 3) st2 = 0; \
            if (i + 1 < NKCH) STSB(st1); \
            if (i + 2 < NKCH) { LDGB(i + 2); CPA(i + 2, st2); CP_COMMIT(); } \
            uint32_t so = stc * STAGEB; \
            compute_chunk(aAf0 + so, aAf1 + so, aAf2 + so, aAf3 + so, \
                          aBf0 + so, aBf1 + so, acc); \
            stc = st1; \
        } \
    }

// ---------------- kernel 3: fc1 GEMM + fused swiglu + coef fold ----------------
// grid (64, NE): n-tile = 64 channels; B rows = 64 up rows + 64 gate rows.
__global__ void __launch_bounds__(256, 2) fc1_mma(const float* __restrict__ w1) {
    extern __shared__ __align__(1024) char smem[];
    float* coefs = (float*)smem;
    float* buf   = (float*)(smem + ST_OFF);   // epilogue exchange, reuses stages

    GEMM_SETUP();

    int e  = blockIdx.y;
    int n0 = blockIdx.x * 64;      // first inter channel of this CTA

    if (tid < T) coefs[tid] = g_coef[e][tid];   // pads = 0

    const float* aglob = &g_xg[e][arow][0] + ab * 4;
    int wrow = (arow < 64) ? (n0 + arow) : (INTER + n0 + (arow - 64));
    const float* bglob = w1 + (size_t)e * (2 * INTER) * H + (size_t)wrow * H + ab * 4;

    GEMM_MAINLOOP();

    // ---- epilogue: exchange via smem, swiglu + coef, tf32-round, store g_act ----
    __syncthreads();
    int g0 = lane >> 2, t4 = lane & 3;
#pragma unroll
    for (int mf = 0; mf < 4; mf++) {
        int m0 = wm * 64 + mf * 16 + g0;
#pragma unroll
        for (int nf = 0; nf < 4; nf++) {
            int j = wn * 32 + nf * 8 + 2 * t4;
            buf[m0 * 132 + j]           = acc[mf][nf][0];
            buf[m0 * 132 + j + 1]       = acc[mf][nf][1];
            buf[(m0 + 8) * 132 + j]     = acc[mf][nf][2];
            buf[(m0 + 8) * 132 + j + 1] = acc[mf][nf][3];
        }
    }
    __syncthreads();
    {
        int m  = tid >> 1;
        int jh = (tid & 1) << 5;          // 0 or 32
        float c = coefs[m];
        const float* row = &buf[m * 132];
#pragma unroll
        for (int q = 0; q < 8; q++) {
            float4 u = *(const float4*)&row[jh + q * 4];        // up   (cols 0..63)
            float4 g = *(const float4*)&row[64 + jh + q * 4];   // gate (cols 64..127)
            uint4 o;
            o.x = f2tf(c * (u.x / (1.0f + __expf(-u.x))) * g.x);
            o.y = f2tf(c * (u.y / (1.0f + __expf(-u.y))) * g.y);
            o.z = f2tf(c * (u.z / (1.0f + __expf(-u.z))) * g.z);
            o.w = f2tf(c * (u.w / (1.0f + __expf(-u.w))) * g.w);
            *(uint4*)&g_act[e][m][n0 + jh + q * 4] = o;
        }
    }
}

// ---------------- kernel 4: fc2 GEMM (4-way K-split) + scatter-add ----------------
// grid (8, 4, NE): 8 hidden-tiles of 128, 4 K-slices of 1024.
__global__ void __launch_bounds__(256, 2) fc2_mma(const float* __restrict__ w2,
                                                  float* __restrict__ out) {
    extern __shared__ __align__(1024) char smem[];
    int* toks = (int*)smem;

    GEMM_SETUP();

    int e     = blockIdx.z;
    int cnt   = g_cnt[e];
    int n0    = blockIdx.x * 128;
    int kbase = blockIdx.y * 1024;

    if (tid < T) toks[tid] = (tid < cnt) ? g_tok[e][tid] : 0;

    const float* aglob = &g_act[e][arow][kbase] + ab * 4;
    const float* bglob = w2 + (size_t)e * H * INTER + (size_t)(n0 + arow) * INTER + kbase + ab * 4;

    GEMM_MAINLOOP();

    int g0 = lane >> 2, t4 = lane & 3;
#pragma unroll
    for (int mf = 0; mf < 4; mf++) {
        int m0 = wm * 64 + mf * 16 + g0;
#pragma unroll
        for (int nf = 0; nf < 4; nf++) {
            int n = n0 + wn * 32 + nf * 8 + 2 * t4;
            if (m0 < cnt) {
                float* o = out + (size_t)toks[m0] * H + n;
                atomicAdd(o,     acc[mf][nf][0]);
                atomicAdd(o + 1, acc[mf][nf][1]);
            }
            if (m0 + 8 < cnt) {
                float* o = out + (size_t)toks[m0 + 8] * H + n;
                atomicAdd(o,     acc[mf][nf][2]);
                atomicAdd(o + 1, acc[mf][nf][3]);
            }
        }
    }
}

// ---------------- launch ----------------
extern "C" void kernel_launch(void* const* d_in, const int* in_sizes, int n_in,
                              void* d_out, int out_size) {
    const float* x       = (const float*)d_in[0];   // [128, 1024]
    const float* routing = (const float*)d_in[1];   // [128, 8]
    const float* w1      = (const float*)d_in[2];   // [8, 8192, 1024]
    const float* w2      = (const float*)d_in[3];   // [8, 1024, 4096]
    float* out = (float*)d_out;                     // [128, 1024]

    cudaFuncSetAttribute(fc1_mma, cudaFuncAttributeMaxDynamicSharedMemorySize, SMEM_BYTES);
    cudaFuncSetAttribute(fc2_mma, cudaFuncAttributeMaxDynamicSharedMemorySize, SMEM_BYTES);

    zero_out_kernel<<<(T * H + 255) / 256, 256>>>(out);
    route_kernel<<<1, T>>>(routing);
    gather_x_kernel<<<NE * T, 256>>>(x);
    fc1_mma<<<dim3(64, NE), 256, SMEM_BYTES>>>(w1);
    fc2_mma<<<dim3(8, 4, NE), 256, SMEM_BYTES>>>(w2, out);
}

// round 9
// speedup vs baseline: 4.4068x; 1.1819x over previous
#include <cuda_runtime.h>
#include <math.h>
#include <stdint.h>

#define T     128
#define H     1024
#define INTER 4096
#define NE    8
#define NKCH  32          // 32 K-chunks of 32 floats = K depth 1024 per CTA

// ---------------- device-global scratch ----------------
__device__ int   g_cnt[NE];
__device__ int   g_tok[NE][T];
__device__ float g_coef[NE][T];          // pad slots never written -> stay 0
__device__ float g_xg[NE][T][H];         // gathered token rows, tf32-rounded (4 MB)
__device__ float g_act[NE][T][INTER];    // coef-scaled swiglu output, tf32-rounded

// ---------------- smem layout (dynamic) ----------------
// [0,512)   coefs (fc1) / toks (fc2)
// stages: 3 x (A 4KB + B 16KB), XOR-swizzled 128B rows
#define ST_OFF   1024
#define STG_B    4096                    // B offset inside a stage
#define STAGEB   20480
#define SMEM_BYTES (1024 + 3 * STAGEB)   // 62464

// ---------------- PTX helpers ----------------
static __device__ __forceinline__ uint32_t smem_u32(const void* p){
    uint32_t a;
    asm("{ .reg .u64 t; cvta.to.shared.u64 t, %1; cvt.u32.u64 %0, t; }" : "=r"(a) : "l"(p));
    return a;
}
#define CP16(d, s)  asm volatile("cp.async.cg.shared.global [%0], [%1], 16;" :: "r"(d), "l"(s) : "memory")
#define CP_COMMIT() asm volatile("cp.async.commit_group;" ::: "memory")
#define CP_WAIT1()  asm volatile("cp.async.wait_group 1;" ::: "memory")
#define CP_WAIT0()  asm volatile("cp.async.wait_group 0;" ::: "memory")

static __device__ __forceinline__ uint32_t f2tf(float x){
    uint32_t r; asm("cvt.rna.tf32.f32 %0, %1;" : "=r"(r) : "f"(x)); return r;
}
static __device__ __forceinline__ void sts_cvt(uint32_t addr, float4 v){
    uint32_t x0 = f2tf(v.x), x1 = f2tf(v.y), x2 = f2tf(v.z), x3 = f2tf(v.w);
    asm volatile("st.shared.v4.b32 [%0], {%1,%2,%3,%4};"
                 :: "r"(addr), "r"(x0), "r"(x1), "r"(x2), "r"(x3) : "memory");
}
#define LDM4(r, addr) \
    asm volatile("ldmatrix.sync.aligned.m8n8.x4.shared.b16 {%0,%1,%2,%3}, [%4];" \
        : "=r"((r)[0]), "=r"((r)[1]), "=r"((r)[2]), "=r"((r)[3]) : "r"(addr))

static __device__ __forceinline__ void mma8(float* d, const uint32_t* a, uint32_t b0, uint32_t b1){
    asm volatile("mma.sync.aligned.m16n8k8.row.col.f32.tf32.tf32.f32 "
        "{%0,%1,%2,%3}, {%4,%5,%6,%7}, {%8,%9}, {%0,%1,%2,%3};"
        : "+f"(d[0]), "+f"(d[1]), "+f"(d[2]), "+f"(d[3])
        : "r"(a[0]), "r"(a[1]), "r"(a[2]), "r"(a[3]), "r"(b0), "r"(b1));
}

// ---------------- kernel 0: zero output ----------------
__global__ void zero_out_kernel(float* __restrict__ out) {
    int i = blockIdx.x * blockDim.x + threadIdx.x;
    if (i < T * H) out[i] = 0.0f;
}

// ---------------- kernel 1: routing ----------------
__global__ void route_kernel(const float* __restrict__ routing) {
    __shared__ int s_cnt[NE];
    int t = threadIdx.x;
    if (t < NE) s_cnt[t] = 0;
    __syncthreads();
    float r[NE];
#pragma unroll
    for (int e = 0; e < NE; e++) r[e] = routing[t * NE + e];
    int i0 = 0;
#pragma unroll
    for (int e = 1; e < NE; e++) if (r[e] > r[i0]) i0 = e;
    int i1 = (i0 == 0) ? 1 : 0;
#pragma unroll
    for (int e = 0; e < NE; e++) if (e != i0 && r[e] > r[i1]) i1 = e;
    float d  = expf(r[i1] - r[i0]);
    float s0 = 1.0f / (1.0f + d);
    float s1 = d / (1.0f + d);
    int p0 = atomicAdd(&s_cnt[i0], 1);
    int p1 = atomicAdd(&s_cnt[i1], 1);
    g_tok[i0][p0] = t;  g_coef[i0][p0] = s0;
    g_tok[i1][p1] = t;  g_coef[i1][p1] = s1;
    __syncthreads();
    if (t < NE) g_cnt[t] = s_cnt[t];
}

// ---------------- kernel 2: gather token rows (tf32-rounded) -> g_xg ----------------
__global__ void gather_x_kernel(const float* __restrict__ x) {
    int bid = blockIdx.x;
    int e = bid >> 7, m = bid & 127;
    int tok = (m < g_cnt[e]) ? g_tok[e][m] : 0;
    float4 v = ((const float4*)(x + (size_t)tok * H))[threadIdx.x];
    uint4 o;
    o.x = f2tf(v.x); o.y = f2tf(v.y); o.z = f2tf(v.z); o.w = f2tf(v.w);
    ((uint4*)&g_xg[e][m][0])[threadIdx.x] = o;
}

// ================= GEMM machinery =================
// CTA tile M=32 x N=128 x Kchunk=32; 8 warps as 2(M) x 4(N), warp tile 16x32.
// Smem data already tf32-rounded; fragments via ldmatrix.b16 (fp32 = b16 pair).
// XOR swizzle: 16B unit u of row r stored at u ^ (r & 7); k-step ks flips bit
// pattern via addr ^ (ks << 5).
static __device__ __forceinline__ void compute_chunk(
        uint32_t aAf, uint32_t b0a, uint32_t b1a, float (&acc)[4][4]) {
#pragma unroll
    for (int ks = 0; ks < 4; ks++) {
        uint32_t x = ks << 5;
        uint32_t a[4], b0[4], b1[4];
        LDM4(a,  aAf ^ x);
        LDM4(b0, b0a ^ x);
        LDM4(b1, b1a ^ x);
        mma8(acc[0], a, b0[0], b0[1]);
        mma8(acc[1], a, b0[2], b0[3]);
        mma8(acc[2], a, b1[0], b1[1]);
        mma8(acc[3], a, b1[2], b1[3]);
    }
}

#define GEMM_SETUP() \
    int tid = threadIdx.x, wid = tid >> 5, lane = tid & 31; \
    int wm = wid >> 2, wn = wid & 3; \
    int ar = tid >> 3, au = tid & 7;            /* A loader: 32 rows x 8 units */ \
    int br = tid >> 1, bu = (tid & 1) * 4;      /* B loader: 128 rows x 2 halves */ \
    uint32_t smemA = smem_u32(smem) + ST_OFF; \
    uint32_t smemB = smemA + STG_B; \
    int ls = lane & 7, h3 = (lane >> 3) & 1, h4 = (lane >> 4) & 1; \
    uint32_t aAf  = smemA + (uint32_t)(wm * 16 + ls + 8 * h3) * 128 + ((uint32_t)(ls ^ h4) << 4); \
    uint32_t aBf0 = smemB + (uint32_t)(wn * 32 + ls + 8 * h4) * 128 + ((uint32_t)(ls ^ h3) << 4); \
    uint32_t aBf1 = aBf0 + 16 * 128; \
    float4 rb0, rb1, rb2, rb3; \
    float acc[4][4]; \
    _Pragma("unroll") for (int _j = 0; _j < 4; _j++) \
    _Pragma("unroll") for (int _q = 0; _q < 4; _q++) acc[_j][_q] = 0.0f;

#define CPA(i, st) \
    CP16(smemA + (st) * STAGEB + ar * 128 + (((au) ^ (ar & 7)) << 4), aglob + (i) * 32)

#define LDGB(i) do { \
        const float4* _p = (const float4*)(bglob + (i) * 32); \
        rb0 = _p[0]; rb1 = _p[1]; rb2 = _p[2]; rb3 = _p[3]; \
    } while (0)

#define STSB(st) do { \
        uint32_t _d = smemB + (st) * STAGEB + br * 128; \
        uint32_t _s = br & 7; \
        sts_cvt(_d + (((bu + 0) ^ _s) << 4), rb0); \
        sts_cvt(_d + (((bu + 1) ^ _s) << 4), rb1); \
        sts_cvt(_d + (((bu + 2) ^ _s) << 4), rb2); \
        sts_cvt(_d + (((bu + 3) ^ _s) << 4), rb3); \
    } while (0)

// 3 stages, 1 barrier/chunk. A via cp.async (pre-rounded source), B via
// LDG -> cvt.rna -> STS riding registers one iteration.
#define GEMM_MAINLOOP() \
    LDGB(0); CPA(0, 0); CP_COMMIT(); \
    STSB(0); \
    LDGB(1); CPA(1, 1); CP_COMMIT(); \
    { \
        int stc = 0; \
        for (int i = 0; i < NKCH; i++) { \
            if (i < NKCH - 1) { CP_WAIT1(); } else { CP_WAIT0(); } \
            __syncthreads(); \
            int st1 = stc + 1; if (st1 == 3) st1 = 0; \
            int st2 = st1 + 1; if (st2 == 3) st2 = 0; \
            if (i + 1 < NKCH) STSB(st1); \
            if (i + 2 < NKCH) { LDGB(i + 2); CPA(i + 2, st2); CP_COMMIT(); } \
            uint32_t so = stc * STAGEB; \
            compute_chunk(aAf + so, aBf0 + so, aBf1 + so, acc); \
            stc = st1; \
        } \
    }

// ---------------- kernel 3: fc1 GEMM + fused swiglu + coef fold ----------------
// grid (4, 64, NE): x = m-tile (fastest -> L2 weight reuse), y = 64-ch n-tile.
__global__ void __launch_bounds__(256, 3) fc1_mma(const float* __restrict__ w1) {
    extern __shared__ __align__(1024) char smem[];
    float* coefs = (float*)smem;

    int e   = blockIdx.z;
    int cnt = g_cnt[e];
    int m0g = blockIdx.x * 32;
    if (m0g >= cnt) return;
    int n0  = blockIdx.y * 64;      // first inter channel of this CTA

    GEMM_SETUP();

    if (tid < 32) coefs[tid] = g_coef[e][m0g + tid];   // pads = 0

    const float* aglob = &g_xg[e][m0g + ar][0] + au * 4;
    int wrow = (br < 64) ? (n0 + br) : (INTER + n0 + (br - 64));
    const float* bglob = w1 + (size_t)e * (2 * INTER) * H + (size_t)wrow * H + bu * 4;

    GEMM_MAINLOOP();

    // ---- epilogue: exchange via smem, swiglu + coef, tf32-round, store g_act ----
    __syncthreads();
    float* buf = (float*)(smem + ST_OFF);   // 32 x 132
    int g0 = lane >> 2, t4 = lane & 3;
#pragma unroll
    for (int nf = 0; nf < 4; nf++) {
        int j  = wn * 32 + nf * 8 + 2 * t4;
        int r0 = wm * 16 + g0;
        buf[r0 * 132 + j]           = acc[nf][0];
        buf[r0 * 132 + j + 1]       = acc[nf][1];
        buf[(r0 + 8) * 132 + j]     = acc[nf][2];
        buf[(r0 + 8) * 132 + j + 1] = acc[nf][3];
    }
    __syncthreads();
    {
        int m  = tid >> 3;
        int cb = (tid & 7) * 8;
        float c = coefs[m];
        const float* row = &buf[m * 132];
#pragma unroll
        for (int q = 0; q < 2; q++) {
            float4 u = *(const float4*)&row[cb + q * 4];        // up   (cols 0..63)
            float4 g = *(const float4*)&row[64 + cb + q * 4];   // gate (cols 64..127)
            uint4 o;
            o.x = f2tf(c * (u.x / (1.0f + __expf(-u.x))) * g.x);
            o.y = f2tf(c * (u.y / (1.0f + __expf(-u.y))) * g.y);
            o.z = f2tf(c * (u.z / (1.0f + __expf(-u.z))) * g.z);
            o.w = f2tf(c * (u.w / (1.0f + __expf(-u.w))) * g.w);
            *(uint4*)&g_act[e][m0g + m][n0 + cb + q * 4] = o;
        }
    }
}

// ---------------- kernel 4: fc2 GEMM (4-way K-split) + scatter-add ----------------
// grid (4, 32, NE): x = m-tile (fastest), y = n-tile(8) x k-slice(4).
__global__ void __launch_bounds__(256, 3) fc2_mma(const float* __restrict__ w2,
                                                  float* __restrict__ out) {
    extern __shared__ __align__(1024) char smem[];
    int* toks = (int*)smem;

    int e   = blockIdx.z;
    int cnt = g_cnt[e];
    int m0g = blockIdx.x * 32;
    if (m0g >= cnt) return;
    int n0    = (blockIdx.y >> 2) * 128;
    int kbase = (blockIdx.y & 3) * 1024;

    GEMM_SETUP();

    if (tid < 32) toks[tid] = (m0g + tid < cnt) ? g_tok[e][m0g + tid] : 0;

    const float* aglob = &g_act[e][m0g + ar][kbase] + au * 4;
    const float* bglob = w2 + (size_t)e * H * INTER + (size_t)(n0 + br) * INTER + kbase + bu * 4;

    GEMM_MAINLOOP();

    int g0 = lane >> 2, t4 = lane & 3;
    int r0 = wm * 16 + g0;
#pragma unroll
    for (int nf = 0; nf < 4; nf++) {
        int n = n0 + wn * 32 + nf * 8 + 2 * t4;
        if (m0g + r0 < cnt) {
            float* o = out + (size_t)toks[r0] * H + n;
            atomicAdd(o,     acc[nf][0]);
            atomicAdd(o + 1, acc[nf][1]);
        }
        if (m0g + r0 + 8 < cnt) {
            float* o = out + (size_t)toks[r0 + 8] * H + n;
            atomicAdd(o,     acc[nf][2]);
            atomicAdd(o + 1, acc[nf][3]);
        }
    }
}

// ---------------- launch ----------------
extern "C" void kernel_launch(void* const* d_in, const int* in_sizes, int n_in,
                              void* d_out, int out_size) {
    const float* x       = (const float*)d_in[0];   // [128, 1024]
    const float* routing = (const float*)d_in[1];   // [128, 8]
    const float* w1      = (const float*)d_in[2];   // [8, 8192, 1024]
    const float* w2      = (const float*)d_in[3];   // [8, 1024, 4096]
    float* out = (float*)d_out;                     // [128, 1024]

    cudaFuncSetAttribute(fc1_mma, cudaFuncAttributeMaxDynamicSharedMemorySize, SMEM_BYTES);
    cudaFuncSetAttribute(fc2_mma, cudaFuncAttributeMaxDynamicSharedMemorySize, SMEM_BYTES);

    zero_out_kernel<<<(T * H + 255) / 256, 256>>>(out);
    route_kernel<<<1, T>>>(routing);
    gather_x_kernel<<<NE * T, 256>>>(x);
    fc1_mma<<<dim3(4, 64, NE), 256, SMEM_BYTES>>>(w1);
    fc2_mma<<<dim3(4, 32, NE), 256, SMEM_BYTES>>>(w2, out);
}